// round 1
// baseline (speedup 1.0000x reference)
#include <cuda_runtime.h>
#include <cstdint>
#include <cstddef>

// Problem constants
constexpr int B_   = 4;
constexpr int T_   = 2048;
constexpr int C_   = 2048;
constexpr int KSZ  = 1024;   // KEY_SIZE (= VALUE_SIZE = H*Dk = H*Dv)
constexpr int H_   = 16;
constexpr int DK_  = 64;
constexpr int M_   = B_ * T_;   // 8192 rows for Q-side GEMMs
// NOTE: B_*C_ == B_*T_ == 8192, so all projection GEMMs share M=8192, N=1024, K=1024

// ---------------------------------------------------------------------------
// Scratch (device globals; no allocations allowed in kernel_launch)
// ---------------------------------------------------------------------------
__device__ float g_q[(size_t)M_ * KSZ];
__device__ float g_k[(size_t)M_ * KSZ];
__device__ float g_v[(size_t)M_ * KSZ];
__device__ float g_attn[(size_t)M_ * KSZ];

// ---------------------------------------------------------------------------
// SGEMM NT: C[m][n] = sum_k A[m*K+k] * W[n*K+k]
// 128x128 tile, BK=8, 256 threads, 8x8 microtile
// ---------------------------------------------------------------------------
__global__ __launch_bounds__(256, 2)
void sgemm_nt_kernel(const float* __restrict__ A, const float* __restrict__ W,
                     float* __restrict__ C, int M, int N, int K) {
    __shared__ float As[8][128];
    __shared__ float Bs[8][128];

    const int tid = threadIdx.x;
    const int tx = tid & 15;          // 0..15
    const int ty = tid >> 4;          // 0..15
    const int r0 = ty * 8;
    const int c0 = tx * 8;
    const int m0 = blockIdx.y * 128;
    const int n0 = blockIdx.x * 128;

    // global load assignment: 256 float4 per operand tile (128 rows x 2 float4)
    const int lrow = tid >> 1;        // 0..127
    const int lk   = (tid & 1) * 4;   // 0 or 4
    const float* Ag = A + (size_t)(m0 + lrow) * K + lk;
    const float* Wg = W + (size_t)(n0 + lrow) * K + lk;

    float acc[8][8];
#pragma unroll
    for (int i = 0; i < 8; i++)
#pragma unroll
        for (int j = 0; j < 8; j++) acc[i][j] = 0.f;

    for (int kt = 0; kt < K; kt += 8) {
        float4 av = *(const float4*)(Ag + kt);
        float4 wv = *(const float4*)(Wg + kt);
        __syncthreads();   // previous compute done before overwrite
        As[lk + 0][lrow] = av.x; As[lk + 1][lrow] = av.y;
        As[lk + 2][lrow] = av.z; As[lk + 3][lrow] = av.w;
        Bs[lk + 0][lrow] = wv.x; Bs[lk + 1][lrow] = wv.y;
        Bs[lk + 2][lrow] = wv.z; Bs[lk + 3][lrow] = wv.w;
        __syncthreads();

#pragma unroll
        for (int kk = 0; kk < 8; kk++) {
            float4 a0 = *(const float4*)&As[kk][r0];
            float4 a1 = *(const float4*)&As[kk][r0 + 4];
            float4 b0 = *(const float4*)&Bs[kk][c0];
            float4 b1 = *(const float4*)&Bs[kk][c0 + 4];
            float a[8] = {a0.x, a0.y, a0.z, a0.w, a1.x, a1.y, a1.z, a1.w};
            float b[8] = {b0.x, b0.y, b0.z, b0.w, b1.x, b1.y, b1.z, b1.w};
#pragma unroll
            for (int i = 0; i < 8; i++)
#pragma unroll
                for (int j = 0; j < 8; j++)
                    acc[i][j] = fmaf(a[i], b[j], acc[i][j]);
        }
    }

#pragma unroll
    for (int i = 0; i < 8; i++) {
        float* Crow = C + (size_t)(m0 + r0 + i) * N + n0 + c0;
        *(float4*)(Crow)     = make_float4(acc[i][0], acc[i][1], acc[i][2], acc[i][3]);
        *(float4*)(Crow + 4) = make_float4(acc[i][4], acc[i][5], acc[i][6], acc[i][7]);
    }
}

// ---------------------------------------------------------------------------
// Flash attention (fp32): per (b,h), 64-row Q tile, loop over 64-key chunks.
// smem: qs [64][64], ks [64][65] (aliased for P), vs [64][64]  -> 49408 bytes
// 256 threads = 16x16, each computes a 4x4 output microtile.
// ---------------------------------------------------------------------------
constexpr int ATTN_SMEM_FLOATS = 64 * 64 + 64 * 65 + 64 * 64;
constexpr int ATTN_SMEM_BYTES  = ATTN_SMEM_FLOATS * 4;

__global__ __launch_bounds__(256, 2)
void attn_kernel(const float* __restrict__ q, const float* __restrict__ k,
                 const float* __restrict__ v, float* __restrict__ o) {
    extern __shared__ float sm[];
    float* qs = sm;                    // [64][64]
    float* ks = sm + 64 * 64;          // [64][65]   (reused as P)
    float* vs = ks + 64 * 65;          // [64][64]

    const int tid = threadIdx.x;
    const int tx = tid & 15;
    const int ty = tid >> 4;
    const int r0 = ty * 4;
    const int c0 = tx * 4;

    const int bh = blockIdx.y;
    const int b  = bh >> 4;
    const int h  = bh & 15;
    const int m0 = blockIdx.x * 64;

    const size_t qbase = ((size_t)(b * T_ + m0)) * KSZ + h * DK_;

    // load Q tile: 1024 float4, 4 per thread
#pragma unroll
    for (int it = 0; it < 4; it++) {
        int idx = tid + it * 256;        // float4 index 0..1023
        int row = idx >> 4;
        int d4  = (idx & 15) * 4;
        float4 qv = *(const float4*)&q[qbase + (size_t)row * KSZ + d4];
        *(float4*)&qs[row * 64 + d4] = qv;
    }

    float acc[4][4];
    float mi[4], li[4];
#pragma unroll
    for (int i = 0; i < 4; i++) {
        mi[i] = -1e30f; li[i] = 0.f;
#pragma unroll
        for (int j = 0; j < 4; j++) acc[i][j] = 0.f;
    }

    for (int ch = 0; ch < C_ / 64; ch++) {
        __syncthreads();   // prior P reads / Q writes complete
        const size_t kbase = ((size_t)(b * C_ + ch * 64)) * KSZ + h * DK_;
#pragma unroll
        for (int it = 0; it < 4; it++) {
            int idx = tid + it * 256;
            int row = idx >> 4;
            int d4  = (idx & 15) * 4;
            float4 kv = *(const float4*)&k[kbase + (size_t)row * KSZ + d4];
            ks[row * 65 + d4 + 0] = kv.x;
            ks[row * 65 + d4 + 1] = kv.y;
            ks[row * 65 + d4 + 2] = kv.z;
            ks[row * 65 + d4 + 3] = kv.w;
            float4 vv = *(const float4*)&v[kbase + (size_t)row * KSZ + d4];
            *(float4*)&vs[row * 64 + d4] = vv;
        }
        __syncthreads();

        // scores s[4][4] = q(r0+i) . k(c0+j)
        float s[4][4];
#pragma unroll
        for (int i = 0; i < 4; i++)
#pragma unroll
            for (int j = 0; j < 4; j++) s[i][j] = 0.f;

#pragma unroll 8
        for (int kk = 0; kk < 64; kk++) {
            float a0 = qs[(r0 + 0) * 64 + kk];
            float a1 = qs[(r0 + 1) * 64 + kk];
            float a2 = qs[(r0 + 2) * 64 + kk];
            float a3 = qs[(r0 + 3) * 64 + kk];
            float b0 = ks[(c0 + 0) * 65 + kk];
            float b1 = ks[(c0 + 1) * 65 + kk];
            float b2 = ks[(c0 + 2) * 65 + kk];
            float b3 = ks[(c0 + 3) * 65 + kk];
            s[0][0] = fmaf(a0, b0, s[0][0]); s[0][1] = fmaf(a0, b1, s[0][1]);
            s[0][2] = fmaf(a0, b2, s[0][2]); s[0][3] = fmaf(a0, b3, s[0][3]);
            s[1][0] = fmaf(a1, b0, s[1][0]); s[1][1] = fmaf(a1, b1, s[1][1]);
            s[1][2] = fmaf(a1, b2, s[1][2]); s[1][3] = fmaf(a1, b3, s[1][3]);
            s[2][0] = fmaf(a2, b0, s[2][0]); s[2][1] = fmaf(a2, b1, s[2][1]);
            s[2][2] = fmaf(a2, b2, s[2][2]); s[2][3] = fmaf(a2, b3, s[2][3]);
            s[3][0] = fmaf(a3, b0, s[3][0]); s[3][1] = fmaf(a3, b1, s[3][1]);
            s[3][2] = fmaf(a3, b2, s[3][2]); s[3][3] = fmaf(a3, b3, s[3][3]);
        }

        // online softmax update (per row; row group = 16 lanes within a half-warp)
#pragma unroll
        for (int i = 0; i < 4; i++) {
            float mx = -1e30f;
#pragma unroll
            for (int j = 0; j < 4; j++) {
                s[i][j] *= 0.125f;                    // 1/sqrt(64)
                mx = fmaxf(mx, s[i][j]);
            }
#pragma unroll
            for (int ofs = 8; ofs >= 1; ofs >>= 1)
                mx = fmaxf(mx, __shfl_xor_sync(0xffffffffu, mx, ofs));
            float nm   = fmaxf(mi[i], mx);
            float corr = __expf(mi[i] - nm);
            float ls = 0.f;
#pragma unroll
            for (int j = 0; j < 4; j++) {
                s[i][j] = __expf(s[i][j] - nm);
                ls += s[i][j];
            }
#pragma unroll
            for (int ofs = 8; ofs >= 1; ofs >>= 1)
                ls += __shfl_xor_sync(0xffffffffu, ls, ofs);
            li[i] = li[i] * corr + ls;
            mi[i] = nm;
#pragma unroll
            for (int j = 0; j < 4; j++) acc[i][j] *= corr;
        }

        __syncthreads();   // all score reads of ks done
        // write P into ks region, layout [row][key] stride 65
#pragma unroll
        for (int i = 0; i < 4; i++)
#pragma unroll
            for (int j = 0; j < 4; j++)
                ks[(r0 + i) * 65 + (c0 + j)] = s[i][j];
        __syncthreads();

        // PV accumulate
#pragma unroll 8
        for (int kk = 0; kk < 64; kk++) {
            float4 vv = *(const float4*)&vs[kk * 64 + c0];
            float p0 = ks[(r0 + 0) * 65 + kk];
            float p1 = ks[(r0 + 1) * 65 + kk];
            float p2 = ks[(r0 + 2) * 65 + kk];
            float p3 = ks[(r0 + 3) * 65 + kk];
            acc[0][0] = fmaf(p0, vv.x, acc[0][0]); acc[0][1] = fmaf(p0, vv.y, acc[0][1]);
            acc[0][2] = fmaf(p0, vv.z, acc[0][2]); acc[0][3] = fmaf(p0, vv.w, acc[0][3]);
            acc[1][0] = fmaf(p1, vv.x, acc[1][0]); acc[1][1] = fmaf(p1, vv.y, acc[1][1]);
            acc[1][2] = fmaf(p1, vv.z, acc[1][2]); acc[1][3] = fmaf(p1, vv.w, acc[1][3]);
            acc[2][0] = fmaf(p2, vv.x, acc[2][0]); acc[2][1] = fmaf(p2, vv.y, acc[2][1]);
            acc[2][2] = fmaf(p2, vv.z, acc[2][2]); acc[2][3] = fmaf(p2, vv.w, acc[2][3]);
            acc[3][0] = fmaf(p3, vv.x, acc[3][0]); acc[3][1] = fmaf(p3, vv.y, acc[3][1]);
            acc[3][2] = fmaf(p3, vv.z, acc[3][2]); acc[3][3] = fmaf(p3, vv.w, acc[3][3]);
        }
    }

    // epilogue: normalize and store
    const size_t obase = ((size_t)(b * T_ + m0)) * KSZ + h * DK_;
#pragma unroll
    for (int i = 0; i < 4; i++) {
        float inv = 1.f / li[i];
        float4 ov = make_float4(acc[i][0] * inv, acc[i][1] * inv,
                                acc[i][2] * inv, acc[i][3] * inv);
        *(float4*)&o[obase + (size_t)(r0 + i) * KSZ + c0] = ov;
    }
}

// ---------------------------------------------------------------------------
// Launch
// ---------------------------------------------------------------------------
extern "C" void kernel_launch(void* const* d_in, const int* /*in_sizes*/, int /*n_in*/,
                              void* d_out, int /*out_size*/) {
    const float* queries = (const float*)d_in[0];
    const float* keys    = (const float*)d_in[1];
    const float* values  = (const float*)d_in[2];
    const float* Wq      = (const float*)d_in[3];
    const float* Wk      = (const float*)d_in[4];
    const float* Wv      = (const float*)d_in[5];
    const float* Wo      = (const float*)d_in[6];
    float* out = (float*)d_out;

    float *qb, *kb, *vb, *ab;
    cudaGetSymbolAddress((void**)&qb, g_q);
    cudaGetSymbolAddress((void**)&kb, g_k);
    cudaGetSymbolAddress((void**)&vb, g_v);
    cudaGetSymbolAddress((void**)&ab, g_attn);

    cudaFuncSetAttribute(attn_kernel, cudaFuncAttributeMaxDynamicSharedMemorySize,
                         ATTN_SMEM_BYTES);

    dim3 gg(KSZ / 128, M_ / 128);   // (8, 64)

    sgemm_nt_kernel<<<gg, 256>>>(queries, Wq, qb, M_, KSZ, KSZ);
    sgemm_nt_kernel<<<gg, 256>>>(keys,    Wk, kb, M_, KSZ, KSZ);
    sgemm_nt_kernel<<<gg, 256>>>(values,  Wv, vb, M_, KSZ, KSZ);

    attn_kernel<<<dim3(T_ / 64, B_ * H_), 256, ATTN_SMEM_BYTES>>>(qb, kb, vb, ab);

    sgemm_nt_kernel<<<gg, 256>>>(ab, Wo, out, M_, KSZ, KSZ);
}

// round 3
// speedup vs baseline: 1.6650x; 1.6650x over previous
#include <cuda_runtime.h>
#include <cstdint>
#include <cstddef>

// Problem constants
constexpr int B_   = 4;
constexpr int T_   = 2048;
constexpr int C_   = 2048;
constexpr int KSZ  = 1024;
constexpr int H_   = 16;
constexpr int DK_  = 64;
constexpr int M_   = B_ * T_;   // 8192

// ---------------------------------------------------------------------------
// Scratch
// ---------------------------------------------------------------------------
__device__ float g_q[(size_t)M_ * KSZ];
__device__ float g_k[(size_t)M_ * KSZ];
__device__ float g_v[(size_t)M_ * KSZ];
__device__ float g_attn[(size_t)M_ * KSZ];

// ---------------------------------------------------------------------------
// Helpers (base-PTX only: sm_103 target has no tcgen05)
// ---------------------------------------------------------------------------
__device__ __forceinline__ uint32_t smem_u32(const void* p) {
    uint32_t a;
    asm("{ .reg .u64 t; cvta.to.shared.u64 t, %1; cvt.u32.u64 %0, t; }" : "=r"(a) : "l"(p));
    return a;
}
__device__ __forceinline__ uint32_t tf32r(float x) {
    uint32_t u;
    asm("cvt.rna.tf32.f32 %0, %1;" : "=r"(u) : "f"(x));
    return u;
}
__device__ __forceinline__ void cp_async16(uint32_t dst, const void* src) {
    asm volatile("cp.async.cg.shared.global [%0], [%1], 16;" :: "r"(dst), "l"(src) : "memory");
}
#define CP_COMMIT()  asm volatile("cp.async.commit_group;" ::: "memory")
#define CP_WAIT_1()  asm volatile("cp.async.wait_group 1;" ::: "memory")

__device__ __forceinline__ void mma_tf32(float* d, const uint32_t* a, const uint32_t* b) {
    asm volatile(
        "mma.sync.aligned.m16n8k8.row.col.f32.tf32.tf32.f32 "
        "{%0,%1,%2,%3}, {%4,%5,%6,%7}, {%8,%9}, {%0,%1,%2,%3};"
        : "+f"(d[0]), "+f"(d[1]), "+f"(d[2]), "+f"(d[3])
        : "r"(a[0]), "r"(a[1]), "r"(a[2]), "r"(a[3]), "r"(b[0]), "r"(b[1]));
}

// ---------------------------------------------------------------------------
// tf32 mma.sync GEMM:  C[m][n] = sum_k A[m][k] * W[n][k]   (NT)
// M=8192, N=1024, K=1024. Block 128x128, BK=32, 3-stage cp.async pipeline.
// 8 warps in 2(m) x 4(n); warp tile 64x32 -> 4 m16 x 4 n8 mma tiles.
// Smem layout: rows of 32 floats (128B) with SW128-style XOR swizzle:
//   word(m,k) = m*32 + ((k&3) | ((((k>>2) ^ (m&7)) & 7) << 2))
// -> all fragment LDS are conflict-free.
// ---------------------------------------------------------------------------
constexpr int BM = 128, BN = 128, BK = 32, STAGES = 3;
constexpr int STAGE_FLOATS = (BM + BN) * BK;            // 8192 floats = 32KB
constexpr int SM_GEMM_BYTES = STAGES * STAGE_FLOATS * 4;  // 98304

__global__ __launch_bounds__(256, 1)
void gemm_tf32_mma(const float* __restrict__ A, const float* __restrict__ W,
                   float* __restrict__ C) {
    extern __shared__ float smf[];
    const uint32_t sbase = smem_u32(smf);

    const int tid = threadIdx.x;
    const int wid = tid >> 5;
    const int lane = tid & 31;
    const int r = lane >> 2;      // 0..7
    const int c = lane & 3;       // 0..3
    const int wm = wid >> 2;      // 0..1  (m dimension)
    const int wn = wid & 3;       // 0..3  (n dimension)

    const int m0 = blockIdx.y * BM;
    const int n0 = blockIdx.x * BN;
    const int NIT = KSZ / BK;     // 32

    // staging: per thread, 4 x 16B chunks of A and 4 of B per stage
    const int srow = tid >> 1;                 // not used; chunk mapping below
    (void)srow;

    auto fetch_stage = [&](int kc, int s) {
        const uint32_t abase = sbase + (uint32_t)(s * STAGE_FLOATS) * 4u;
        const uint32_t bbase = abase + (uint32_t)(BM * BK) * 4u;
#pragma unroll
        for (int t = 0; t < 4; t++) {
            int idx = tid + t * 256;           // 0..1023
            int row = idx >> 3;                // 0..127
            int c16 = idx & 7;                 // 16B chunk in row
            uint32_t doff = (uint32_t)(row * 128 + ((c16 ^ (row & 7)) << 4));
            cp_async16(abase + doff, &A[(size_t)(m0 + row) * KSZ + kc * BK + c16 * 4]);
        }
#pragma unroll
        for (int t = 0; t < 4; t++) {
            int idx = tid + t * 256;
            int row = idx >> 3;
            int c16 = idx & 7;
            uint32_t doff = (uint32_t)(row * 128 + ((c16 ^ (row & 7)) << 4));
            cp_async16(bbase + doff, &W[(size_t)(n0 + row) * KSZ + kc * BK + c16 * 4]);
        }
    };

    float acc[4][4][4];
#pragma unroll
    for (int i = 0; i < 4; i++)
#pragma unroll
        for (int j = 0; j < 4; j++)
#pragma unroll
            for (int t = 0; t < 4; t++) acc[i][j][t] = 0.f;

    // prologue: fill 2 stages
    fetch_stage(0, 0); CP_COMMIT();
    fetch_stage(1, 1); CP_COMMIT();

    for (int kt = 0; kt < NIT; kt++) {
        CP_WAIT_1();
        __syncthreads();

        // prefetch stage kt+2
        if (kt + 2 < NIT) fetch_stage(kt + 2, (kt + 2) % STAGES);
        CP_COMMIT();

        const int s = kt % STAGES;
        const float* As = smf + s * STAGE_FLOATS;
        const float* Bs = As + BM * BK;

#pragma unroll
        for (int ks = 0; ks < 4; ks++) {
            const int kx0 = c | ((((2 * ks) ^ r) & 7) << 2);
            const int kx1 = c | ((((2 * ks + 1) ^ r) & 7) << 2);

            uint32_t afr[4][4];
            uint32_t bfr[4][2];
#pragma unroll
            for (int i = 0; i < 4; i++) {
                const int m = wm * 64 + i * 16 + r;
                afr[i][0] = tf32r(As[m * 32 + kx0]);
                afr[i][1] = tf32r(As[(m + 8) * 32 + kx0]);
                afr[i][2] = tf32r(As[m * 32 + kx1]);
                afr[i][3] = tf32r(As[(m + 8) * 32 + kx1]);
            }
#pragma unroll
            for (int j = 0; j < 4; j++) {
                const int n = wn * 32 + j * 8 + r;
                bfr[j][0] = tf32r(Bs[n * 32 + kx0]);
                bfr[j][1] = tf32r(Bs[n * 32 + kx1]);
            }
#pragma unroll
            for (int i = 0; i < 4; i++)
#pragma unroll
                for (int j = 0; j < 4; j++)
                    mma_tf32(acc[i][j], afr[i], bfr[j]);
        }
        __syncthreads();
    }

    // epilogue: c0,c1 at (row, col*2..+1), c2,c3 at (row+8, ...)
#pragma unroll
    for (int i = 0; i < 4; i++) {
        const int row = m0 + wm * 64 + i * 16 + r;
#pragma unroll
        for (int j = 0; j < 4; j++) {
            const int col = n0 + wn * 32 + j * 8 + c * 2;
            float* p0 = C + (size_t)row * KSZ + col;
            float* p1 = C + (size_t)(row + 8) * KSZ + col;
            asm volatile("st.global.v2.f32 [%0], {%1,%2};" :: "l"(p0),
                         "f"(acc[i][j][0]), "f"(acc[i][j][1]) : "memory");
            asm volatile("st.global.v2.f32 [%0], {%1,%2};" :: "l"(p1),
                         "f"(acc[i][j][2]), "f"(acc[i][j][3]) : "memory");
        }
    }
}

// ---------------------------------------------------------------------------
// Flash attention (fp32) — unchanged (passing baseline)
// ---------------------------------------------------------------------------
constexpr int ATTN_SMEM_FLOATS = 64 * 64 + 64 * 65 + 64 * 64;
constexpr int ATTN_SMEM_BYTES  = ATTN_SMEM_FLOATS * 4;

__global__ __launch_bounds__(256, 2)
void attn_kernel(const float* __restrict__ q, const float* __restrict__ k,
                 const float* __restrict__ v, float* __restrict__ o) {
    extern __shared__ float sm[];
    float* qs = sm;
    float* ks = sm + 64 * 64;
    float* vs = ks + 64 * 65;

    const int tid = threadIdx.x;
    const int tx = tid & 15;
    const int ty = tid >> 4;
    const int r0 = ty * 4;
    const int c0 = tx * 4;

    const int bh = blockIdx.y;
    const int b  = bh >> 4;
    const int h  = bh & 15;
    const int m0 = blockIdx.x * 64;

    const size_t qbase = ((size_t)(b * T_ + m0)) * KSZ + h * DK_;

#pragma unroll
    for (int it = 0; it < 4; it++) {
        int idx = tid + it * 256;
        int row = idx >> 4;
        int d4  = (idx & 15) * 4;
        float4 qv = *(const float4*)&q[qbase + (size_t)row * KSZ + d4];
        *(float4*)&qs[row * 64 + d4] = qv;
    }

    float acc[4][4];
    float mi[4], li[4];
#pragma unroll
    for (int i = 0; i < 4; i++) {
        mi[i] = -1e30f; li[i] = 0.f;
#pragma unroll
        for (int j = 0; j < 4; j++) acc[i][j] = 0.f;
    }

    for (int ch = 0; ch < C_ / 64; ch++) {
        __syncthreads();
        const size_t kbase = ((size_t)(b * C_ + ch * 64)) * KSZ + h * DK_;
#pragma unroll
        for (int it = 0; it < 4; it++) {
            int idx = tid + it * 256;
            int row = idx >> 4;
            int d4  = (idx & 15) * 4;
            float4 kv = *(const float4*)&k[kbase + (size_t)row * KSZ + d4];
            ks[row * 65 + d4 + 0] = kv.x;
            ks[row * 65 + d4 + 1] = kv.y;
            ks[row * 65 + d4 + 2] = kv.z;
            ks[row * 65 + d4 + 3] = kv.w;
            float4 vv = *(const float4*)&v[kbase + (size_t)row * KSZ + d4];
            *(float4*)&vs[row * 64 + d4] = vv;
        }
        __syncthreads();

        float s[4][4];
#pragma unroll
        for (int i = 0; i < 4; i++)
#pragma unroll
            for (int j = 0; j < 4; j++) s[i][j] = 0.f;

#pragma unroll 8
        for (int kk = 0; kk < 64; kk++) {
            float a0 = qs[(r0 + 0) * 64 + kk];
            float a1 = qs[(r0 + 1) * 64 + kk];
            float a2 = qs[(r0 + 2) * 64 + kk];
            float a3 = qs[(r0 + 3) * 64 + kk];
            float b0 = ks[(c0 + 0) * 65 + kk];
            float b1 = ks[(c0 + 1) * 65 + kk];
            float b2 = ks[(c0 + 2) * 65 + kk];
            float b3 = ks[(c0 + 3) * 65 + kk];
            s[0][0] = fmaf(a0, b0, s[0][0]); s[0][1] = fmaf(a0, b1, s[0][1]);
            s[0][2] = fmaf(a0, b2, s[0][2]); s[0][3] = fmaf(a0, b3, s[0][3]);
            s[1][0] = fmaf(a1, b0, s[1][0]); s[1][1] = fmaf(a1, b1, s[1][1]);
            s[1][2] = fmaf(a1, b2, s[1][2]); s[1][3] = fmaf(a1, b3, s[1][3]);
            s[2][0] = fmaf(a2, b0, s[2][0]); s[2][1] = fmaf(a2, b1, s[2][1]);
            s[2][2] = fmaf(a2, b2, s[2][2]); s[2][3] = fmaf(a2, b3, s[2][3]);
            s[3][0] = fmaf(a3, b0, s[3][0]); s[3][1] = fmaf(a3, b1, s[3][1]);
            s[3][2] = fmaf(a3, b2, s[3][2]); s[3][3] = fmaf(a3, b3, s[3][3]);
        }

#pragma unroll
        for (int i = 0; i < 4; i++) {
            float mx = -1e30f;
#pragma unroll
            for (int j = 0; j < 4; j++) {
                s[i][j] *= 0.125f;
                mx = fmaxf(mx, s[i][j]);
            }
#pragma unroll
            for (int ofs = 8; ofs >= 1; ofs >>= 1)
                mx = fmaxf(mx, __shfl_xor_sync(0xffffffffu, mx, ofs));
            float nm   = fmaxf(mi[i], mx);
            float corr = __expf(mi[i] - nm);
            float ls = 0.f;
#pragma unroll
            for (int j = 0; j < 4; j++) {
                s[i][j] = __expf(s[i][j] - nm);
                ls += s[i][j];
            }
#pragma unroll
            for (int ofs = 8; ofs >= 1; ofs >>= 1)
                ls += __shfl_xor_sync(0xffffffffu, ls, ofs);
            li[i] = li[i] * corr + ls;
            mi[i] = nm;
#pragma unroll
            for (int j = 0; j < 4; j++) acc[i][j] *= corr;
        }

        __syncthreads();
#pragma unroll
        for (int i = 0; i < 4; i++)
#pragma unroll
            for (int j = 0; j < 4; j++)
                ks[(r0 + i) * 65 + (c0 + j)] = s[i][j];
        __syncthreads();

#pragma unroll 8
        for (int kk = 0; kk < 64; kk++) {
            float4 vv = *(const float4*)&vs[kk * 64 + c0];
            float p0 = ks[(r0 + 0) * 65 + kk];
            float p1 = ks[(r0 + 1) * 65 + kk];
            float p2 = ks[(r0 + 2) * 65 + kk];
            float p3 = ks[(r0 + 3) * 65 + kk];
            acc[0][0] = fmaf(p0, vv.x, acc[0][0]); acc[0][1] = fmaf(p0, vv.y, acc[0][1]);
            acc[0][2] = fmaf(p0, vv.z, acc[0][2]); acc[0][3] = fmaf(p0, vv.w, acc[0][3]);
            acc[1][0] = fmaf(p1, vv.x, acc[1][0]); acc[1][1] = fmaf(p1, vv.y, acc[1][1]);
            acc[1][2] = fmaf(p1, vv.z, acc[1][2]); acc[1][3] = fmaf(p1, vv.w, acc[1][3]);
            acc[2][0] = fmaf(p2, vv.x, acc[2][0]); acc[2][1] = fmaf(p2, vv.y, acc[2][1]);
            acc[2][2] = fmaf(p2, vv.z, acc[2][2]); acc[2][3] = fmaf(p2, vv.w, acc[2][3]);
            acc[3][0] = fmaf(p3, vv.x, acc[3][0]); acc[3][1] = fmaf(p3, vv.y, acc[3][1]);
            acc[3][2] = fmaf(p3, vv.z, acc[3][2]); acc[3][3] = fmaf(p3, vv.w, acc[3][3]);
        }
    }

    const size_t obase = ((size_t)(b * T_ + m0)) * KSZ + h * DK_;
#pragma unroll
    for (int i = 0; i < 4; i++) {
        float inv = 1.f / li[i];
        float4 ov = make_float4(acc[i][0] * inv, acc[i][1] * inv,
                                acc[i][2] * inv, acc[i][3] * inv);
        *(float4*)&o[obase + (size_t)(r0 + i) * KSZ + c0] = ov;
    }
}

// ---------------------------------------------------------------------------
// Launch
// ---------------------------------------------------------------------------
extern "C" void kernel_launch(void* const* d_in, const int* /*in_sizes*/, int /*n_in*/,
                              void* d_out, int /*out_size*/) {
    const float* queries = (const float*)d_in[0];
    const float* keys    = (const float*)d_in[1];
    const float* values  = (const float*)d_in[2];
    const float* Wq      = (const float*)d_in[3];
    const float* Wk      = (const float*)d_in[4];
    const float* Wv      = (const float*)d_in[5];
    const float* Wo      = (const float*)d_in[6];
    float* out = (float*)d_out;

    float *qb, *kb, *vb, *ab;
    cudaGetSymbolAddress((void**)&qb, g_q);
    cudaGetSymbolAddress((void**)&kb, g_k);
    cudaGetSymbolAddress((void**)&vb, g_v);
    cudaGetSymbolAddress((void**)&ab, g_attn);

    cudaFuncSetAttribute(gemm_tf32_mma, cudaFuncAttributeMaxDynamicSharedMemorySize,
                         SM_GEMM_BYTES);
    cudaFuncSetAttribute(attn_kernel, cudaFuncAttributeMaxDynamicSharedMemorySize,
                         ATTN_SMEM_BYTES);

    dim3 gg(KSZ / BN, M_ / BM);   // (8, 64)

    gemm_tf32_mma<<<gg, 256, SM_GEMM_BYTES>>>(queries, Wq, qb);
    gemm_tf32_mma<<<gg, 256, SM_GEMM_BYTES>>>(keys,    Wk, kb);
    gemm_tf32_mma<<<gg, 256, SM_GEMM_BYTES>>>(values,  Wv, vb);

    attn_kernel<<<dim3(T_ / 64, B_ * H_), 256, ATTN_SMEM_BYTES>>>(qb, kb, vb, ab);

    gemm_tf32_mma<<<gg, 256, SM_GEMM_BYTES>>>(ab, Wo, out);
}

// round 5
// speedup vs baseline: 3.7159x; 2.2318x over previous
#include <cuda_runtime.h>
#include <cstdint>
#include <cstddef>

// Problem constants
constexpr int B_   = 4;
constexpr int T_   = 2048;
constexpr int C_   = 2048;
constexpr int KSZ  = 1024;
constexpr int H_   = 16;
constexpr int DK_  = 64;
constexpr int M_   = B_ * T_;   // 8192

// ---------------------------------------------------------------------------
// Scratch
// ---------------------------------------------------------------------------
__device__ float g_q[(size_t)M_ * KSZ];
__device__ float g_k[(size_t)M_ * KSZ];
__device__ float g_v[(size_t)M_ * KSZ];
__device__ float g_attn[(size_t)M_ * KSZ];

// ---------------------------------------------------------------------------
// Helpers (base-PTX only: sm_103 target has no tcgen05)
// ---------------------------------------------------------------------------
__device__ __forceinline__ uint32_t smem_u32(const void* p) {
    uint32_t a;
    asm("{ .reg .u64 t; cvta.to.shared.u64 t, %1; cvt.u32.u64 %0, t; }" : "=r"(a) : "l"(p));
    return a;
}
__device__ __forceinline__ uint32_t tf32r(float x) {
    uint32_t u;
    asm("cvt.rna.tf32.f32 %0, %1;" : "=r"(u) : "f"(x));
    return u;
}
__device__ __forceinline__ void cp_async16(uint32_t dst, const void* src) {
    asm volatile("cp.async.cg.shared.global [%0], [%1], 16;" :: "r"(dst), "l"(src) : "memory");
}
#define CP_COMMIT()  asm volatile("cp.async.commit_group;" ::: "memory")
#define CP_WAIT_1()  asm volatile("cp.async.wait_group 1;" ::: "memory")

__device__ __forceinline__ void mma_tf32(float* d, const uint32_t* a, const uint32_t* b) {
    asm volatile(
        "mma.sync.aligned.m16n8k8.row.col.f32.tf32.tf32.f32 "
        "{%0,%1,%2,%3}, {%4,%5,%6,%7}, {%8,%9}, {%0,%1,%2,%3};"
        : "+f"(d[0]), "+f"(d[1]), "+f"(d[2]), "+f"(d[3])
        : "r"(a[0]), "r"(a[1]), "r"(a[2]), "r"(a[3]), "r"(b[0]), "r"(b[1]));
}

// ---------------------------------------------------------------------------
// tf32 mma.sync GEMM (passing @ round 3)
// ---------------------------------------------------------------------------
constexpr int BM = 128, BN = 128, BK = 32, STAGES = 3;
constexpr int STAGE_FLOATS = (BM + BN) * BK;
constexpr int SM_GEMM_BYTES = STAGES * STAGE_FLOATS * 4;

__global__ __launch_bounds__(256, 1)
void gemm_tf32_mma(const float* __restrict__ A, const float* __restrict__ W,
                   float* __restrict__ C) {
    extern __shared__ float smf[];
    const uint32_t sbase = smem_u32(smf);

    const int tid = threadIdx.x;
    const int wid = tid >> 5;
    const int lane = tid & 31;
    const int r = lane >> 2;
    const int c = lane & 3;
    const int wm = wid >> 2;
    const int wn = wid & 3;

    const int m0 = blockIdx.y * BM;
    const int n0 = blockIdx.x * BN;
    const int NIT = KSZ / BK;

    auto fetch_stage = [&](int kc, int s) {
        const uint32_t abase = sbase + (uint32_t)(s * STAGE_FLOATS) * 4u;
        const uint32_t bbase = abase + (uint32_t)(BM * BK) * 4u;
#pragma unroll
        for (int t = 0; t < 4; t++) {
            int idx = tid + t * 256;
            int row = idx >> 3;
            int c16 = idx & 7;
            uint32_t doff = (uint32_t)(row * 128 + ((c16 ^ (row & 7)) << 4));
            cp_async16(abase + doff, &A[(size_t)(m0 + row) * KSZ + kc * BK + c16 * 4]);
        }
#pragma unroll
        for (int t = 0; t < 4; t++) {
            int idx = tid + t * 256;
            int row = idx >> 3;
            int c16 = idx & 7;
            uint32_t doff = (uint32_t)(row * 128 + ((c16 ^ (row & 7)) << 4));
            cp_async16(bbase + doff, &W[(size_t)(n0 + row) * KSZ + kc * BK + c16 * 4]);
        }
    };

    float acc[4][4][4];
#pragma unroll
    for (int i = 0; i < 4; i++)
#pragma unroll
        for (int j = 0; j < 4; j++)
#pragma unroll
            for (int t = 0; t < 4; t++) acc[i][j][t] = 0.f;

    fetch_stage(0, 0); CP_COMMIT();
    fetch_stage(1, 1); CP_COMMIT();

    for (int kt = 0; kt < NIT; kt++) {
        CP_WAIT_1();
        __syncthreads();

        if (kt + 2 < NIT) fetch_stage(kt + 2, (kt + 2) % STAGES);
        CP_COMMIT();

        const int s = kt % STAGES;
        const float* As = smf + s * STAGE_FLOATS;
        const float* Bs = As + BM * BK;

#pragma unroll
        for (int ks = 0; ks < 4; ks++) {
            const int kx0 = c | ((((2 * ks) ^ r) & 7) << 2);
            const int kx1 = c | ((((2 * ks + 1) ^ r) & 7) << 2);

            uint32_t afr[4][4];
            uint32_t bfr[4][2];
#pragma unroll
            for (int i = 0; i < 4; i++) {
                const int m = wm * 64 + i * 16 + r;
                afr[i][0] = tf32r(As[m * 32 + kx0]);
                afr[i][1] = tf32r(As[(m + 8) * 32 + kx0]);
                afr[i][2] = tf32r(As[m * 32 + kx1]);
                afr[i][3] = tf32r(As[(m + 8) * 32 + kx1]);
            }
#pragma unroll
            for (int j = 0; j < 4; j++) {
                const int n = wn * 32 + j * 8 + r;
                bfr[j][0] = tf32r(Bs[n * 32 + kx0]);
                bfr[j][1] = tf32r(Bs[n * 32 + kx1]);
            }
#pragma unroll
            for (int i = 0; i < 4; i++)
#pragma unroll
                for (int j = 0; j < 4; j++)
                    mma_tf32(acc[i][j], afr[i], bfr[j]);
        }
        __syncthreads();
    }

#pragma unroll
    for (int i = 0; i < 4; i++) {
        const int row = m0 + wm * 64 + i * 16 + r;
#pragma unroll
        for (int j = 0; j < 4; j++) {
            const int col = n0 + wn * 32 + j * 8 + c * 2;
            float* p0 = C + (size_t)row * KSZ + col;
            float* p1 = C + (size_t)(row + 8) * KSZ + col;
            asm volatile("st.global.v2.f32 [%0], {%1,%2};" :: "l"(p0),
                         "f"(acc[i][j][0]), "f"(acc[i][j][1]) : "memory");
            asm volatile("st.global.v2.f32 [%0], {%1,%2};" :: "l"(p1),
                         "f"(acc[i][j][2]), "f"(acc[i][j][3]) : "memory");
        }
    }
}

// ---------------------------------------------------------------------------
// Flash attention with mma.sync tf32.
// CTA: one (b,h), 128 query rows. 8 warps x 16 rows. 64-key chunks, 2-stage
// cp.async double buffer for K/V. P goes through warp-private smem.
// Pads: Q/K/P rows 68 floats (bank=4r+c bijective), V rows 72 (bank=8c+r).
// ---------------------------------------------------------------------------
constexpr int PADQ = 68;
constexpr int PADV = 72;
constexpr int OFF_Q = 0;
constexpr int OFF_K = 8704;
constexpr int OFF_V = OFF_K + 2 * 64 * PADQ;
constexpr int OFF_P = OFF_V + 2 * 64 * PADV;
constexpr int ATTN_SMEM_FLOATS2 = OFF_P + 128 * PADQ;
constexpr int ATTN_SMEM_BYTES2 = ATTN_SMEM_FLOATS2 * 4;

__global__ __launch_bounds__(256, 1)
void attn_mma_kernel(const float* __restrict__ q, const float* __restrict__ k,
                     const float* __restrict__ v, float* __restrict__ o) {
    extern __shared__ float smf[];
    const uint32_t sbase = smem_u32(smf);

    const int tid = threadIdx.x;
    const int wid = tid >> 5;
    const int lane = tid & 31;
    const int r = lane >> 2;
    const int c = lane & 3;
    const int wrow = wid * 16;

    const int bh = blockIdx.y;
    const int b  = bh >> 4;
    const int h  = bh & 15;
    const int m0 = blockIdx.x * 128;

    const float* qg = q + ((size_t)(b * T_) + m0) * KSZ + h * DK_;
    const float* kg0 = k + ((size_t)(b * C_)) * KSZ + h * DK_;

    auto fetchKV = [&](int ch, int s) {
        const float* kg = kg0 + (size_t)(ch * 64) * KSZ;
        const float* vg = v + ((size_t)(b * C_) + ch * 64) * KSZ + h * DK_;
        const uint32_t kb = sbase + (uint32_t)(OFF_K + s * 64 * PADQ) * 4u;
        const uint32_t vb = sbase + (uint32_t)(OFF_V + s * 64 * PADV) * 4u;
#pragma unroll
        for (int t = 0; t < 4; t++) {
            int idx = tid + t * 256;
            int row = idx >> 4;
            int c16 = idx & 15;
            cp_async16(kb + (uint32_t)(row * (PADQ * 4) + c16 * 16),
                       kg + (size_t)row * KSZ + c16 * 4);
            cp_async16(vb + (uint32_t)(row * (PADV * 4) + c16 * 16),
                       vg + (size_t)row * KSZ + c16 * 4);
        }
    };

#pragma unroll
    for (int t = 0; t < 8; t++) {
        int idx = tid + t * 256;
        int row = idx >> 4;
        int c16 = idx & 15;
        cp_async16(sbase + (uint32_t)(OFF_Q * 4 + row * (PADQ * 4) + c16 * 16),
                   qg + (size_t)row * KSZ + c16 * 4);
    }
    fetchKV(0, 0);
    CP_COMMIT();

    uint32_t qfr[8][4];
    float oacc[8][4];
    float mi0 = -1e30f, mi1 = -1e30f, li0 = 0.f, li1 = 0.f;
#pragma unroll
    for (int j = 0; j < 8; j++)
#pragma unroll
        for (int t = 0; t < 4; t++) oacc[j][t] = 0.f;

    const int NC = C_ / 64;
    for (int ch = 0; ch < NC; ch++) {
        if (ch + 1 < NC) fetchKV(ch + 1, (ch + 1) & 1);
        CP_COMMIT();
        CP_WAIT_1();
        __syncthreads();

        if (ch == 0) {
            const uint32_t* Qs = reinterpret_cast<const uint32_t*>(smf + OFF_Q);
#pragma unroll
            for (int ks = 0; ks < 8; ks++) {
                qfr[ks][0] = Qs[(wrow + r) * PADQ + ks * 8 + c];
                qfr[ks][1] = Qs[(wrow + r + 8) * PADQ + ks * 8 + c];
                qfr[ks][2] = Qs[(wrow + r) * PADQ + ks * 8 + c + 4];
                qfr[ks][3] = Qs[(wrow + r + 8) * PADQ + ks * 8 + c + 4];
            }
        }

        const uint32_t* Kc = reinterpret_cast<const uint32_t*>(smf + OFF_K + (ch & 1) * 64 * PADQ);
        const uint32_t* Vc = reinterpret_cast<const uint32_t*>(smf + OFF_V + (ch & 1) * 64 * PADV);

        // ---- S = Q K^T ----
        float sacc[8][4];
#pragma unroll
        for (int j = 0; j < 8; j++)
#pragma unroll
            for (int t = 0; t < 4; t++) sacc[j][t] = 0.f;

#pragma unroll
        for (int ks = 0; ks < 8; ks++) {
            uint32_t bfr[8][2];
#pragma unroll
            for (int j = 0; j < 8; j++) {
                bfr[j][0] = Kc[(j * 8 + r) * PADQ + ks * 8 + c];
                bfr[j][1] = Kc[(j * 8 + r) * PADQ + ks * 8 + c + 4];
            }
#pragma unroll
            for (int j = 0; j < 8; j++)
                mma_tf32(sacc[j], qfr[ks], bfr[j]);
        }

        // ---- online softmax ----
        float mx0 = -1e30f, mx1 = -1e30f;
#pragma unroll
        for (int j = 0; j < 8; j++) {
            sacc[j][0] *= 0.125f; sacc[j][1] *= 0.125f;
            sacc[j][2] *= 0.125f; sacc[j][3] *= 0.125f;
            mx0 = fmaxf(mx0, fmaxf(sacc[j][0], sacc[j][1]));
            mx1 = fmaxf(mx1, fmaxf(sacc[j][2], sacc[j][3]));
        }
        mx0 = fmaxf(mx0, __shfl_xor_sync(0xffffffffu, mx0, 1));
        mx0 = fmaxf(mx0, __shfl_xor_sync(0xffffffffu, mx0, 2));
        mx1 = fmaxf(mx1, __shfl_xor_sync(0xffffffffu, mx1, 1));
        mx1 = fmaxf(mx1, __shfl_xor_sync(0xffffffffu, mx1, 2));

        const float nm0 = fmaxf(mi0, mx0);
        const float nm1 = fmaxf(mi1, mx1);
        const float corr0 = __expf(mi0 - nm0);
        const float corr1 = __expf(mi1 - nm1);
        mi0 = nm0; mi1 = nm1;

        float ls0 = 0.f, ls1 = 0.f;
#pragma unroll
        for (int j = 0; j < 8; j++) {
            sacc[j][0] = __uint_as_float(tf32r(__expf(sacc[j][0] - nm0)));
            sacc[j][1] = __uint_as_float(tf32r(__expf(sacc[j][1] - nm0)));
            sacc[j][2] = __uint_as_float(tf32r(__expf(sacc[j][2] - nm1)));
            sacc[j][3] = __uint_as_float(tf32r(__expf(sacc[j][3] - nm1)));
            ls0 += sacc[j][0] + sacc[j][1];
            ls1 += sacc[j][2] + sacc[j][3];
        }
        ls0 += __shfl_xor_sync(0xffffffffu, ls0, 1);
        ls0 += __shfl_xor_sync(0xffffffffu, ls0, 2);
        ls1 += __shfl_xor_sync(0xffffffffu, ls1, 1);
        ls1 += __shfl_xor_sync(0xffffffffu, ls1, 2);
        li0 = li0 * corr0 + ls0;
        li1 = li1 * corr1 + ls1;

#pragma unroll
        for (int j = 0; j < 8; j++) {
            oacc[j][0] *= corr0; oacc[j][1] *= corr0;
            oacc[j][2] *= corr1; oacc[j][3] *= corr1;
        }

        // ---- P to warp-private smem ----
        float* Ps = smf + OFF_P;
#pragma unroll
        for (int j = 0; j < 8; j++) {
            *reinterpret_cast<float2*>(&Ps[(wrow + r) * PADQ + j * 8 + 2 * c]) =
                make_float2(sacc[j][0], sacc[j][1]);
            *reinterpret_cast<float2*>(&Ps[(wrow + r + 8) * PADQ + j * 8 + 2 * c]) =
                make_float2(sacc[j][2], sacc[j][3]);
        }
        __syncwarp();

        // ---- O += P V ----
        const uint32_t* Pu = reinterpret_cast<const uint32_t*>(smf + OFF_P);
#pragma unroll
        for (int kx = 0; kx < 8; kx++) {
            uint32_t afr[4];
            afr[0] = Pu[(wrow + r) * PADQ + kx * 8 + c];
            afr[1] = Pu[(wrow + r + 8) * PADQ + kx * 8 + c];
            afr[2] = Pu[(wrow + r) * PADQ + kx * 8 + c + 4];
            afr[3] = Pu[(wrow + r + 8) * PADQ + kx * 8 + c + 4];
            uint32_t bfr[8][2];
#pragma unroll
            for (int j = 0; j < 8; j++) {
                bfr[j][0] = Vc[(kx * 8 + c) * PADV + j * 8 + r];
                bfr[j][1] = Vc[(kx * 8 + c + 4) * PADV + j * 8 + r];
            }
#pragma unroll
            for (int j = 0; j < 8; j++)
                mma_tf32(oacc[j], afr, bfr[j]);
        }

        __syncthreads();
    }

    // ---- epilogue ----
    const float inv0 = 1.f / li0;
    const float inv1 = 1.f / li1;
    float* og = o + ((size_t)(b * T_) + m0) * KSZ + h * DK_;
#pragma unroll
    for (int j = 0; j < 8; j++) {
        float* p0 = og + (size_t)(wrow + r) * KSZ + j * 8 + 2 * c;
        float* p1 = og + (size_t)(wrow + r + 8) * KSZ + j * 8 + 2 * c;
        asm volatile("st.global.v2.f32 [%0], {%1,%2};" :: "l"(p0),
                     "f"(oacc[j][0] * inv0), "f"(oacc[j][1] * inv0) : "memory");
        asm volatile("st.global.v2.f32 [%0], {%1,%2};" :: "l"(p1),
                     "f"(oacc[j][2] * inv1), "f"(oacc[j][3] * inv1) : "memory");
    }
}

// ---------------------------------------------------------------------------
// Launch
// ---------------------------------------------------------------------------
extern "C" void kernel_launch(void* const* d_in, const int* /*in_sizes*/, int /*n_in*/,
                              void* d_out, int /*out_size*/) {
    const float* queries = (const float*)d_in[0];
    const float* keys    = (const float*)d_in[1];
    const float* values  = (const float*)d_in[2];
    const float* Wq      = (const float*)d_in[3];
    const float* Wk      = (const float*)d_in[4];
    const float* Wv      = (const float*)d_in[5];
    const float* Wo      = (const float*)d_in[6];
    float* out = (float*)d_out;

    float *qb, *kb, *vb, *ab;
    cudaGetSymbolAddress((void**)&qb, g_q);
    cudaGetSymbolAddress((void**)&kb, g_k);
    cudaGetSymbolAddress((void**)&vb, g_v);
    cudaGetSymbolAddress((void**)&ab, g_attn);

    cudaFuncSetAttribute(gemm_tf32_mma, cudaFuncAttributeMaxDynamicSharedMemorySize,
                         SM_GEMM_BYTES);
    cudaFuncSetAttribute(attn_mma_kernel, cudaFuncAttributeMaxDynamicSharedMemorySize,
                         ATTN_SMEM_BYTES2);

    dim3 gg(KSZ / BN, M_ / BM);   // (8, 64)

    gemm_tf32_mma<<<gg, 256, SM_GEMM_BYTES>>>(queries, Wq, qb);
    gemm_tf32_mma<<<gg, 256, SM_GEMM_BYTES>>>(keys,    Wk, kb);
    gemm_tf32_mma<<<gg, 256, SM_GEMM_BYTES>>>(values,  Wv, vb);

    attn_mma_kernel<<<dim3(T_ / 128, B_ * H_), 256, ATTN_SMEM_BYTES2>>>(qb, kb, vb, ab);

    gemm_tf32_mma<<<gg, 256, SM_GEMM_BYTES>>>(ab, Wo, out);
}

// round 6
// speedup vs baseline: 5.1924x; 1.3973x over previous
#include <cuda_runtime.h>
#include <cuda_fp16.h>
#include <cstdint>
#include <cstddef>

// Problem constants
constexpr int B_   = 4;
constexpr int T_   = 2048;
constexpr int C_   = 2048;
constexpr int KSZ  = 1024;
constexpr int H_   = 16;
constexpr int DK_  = 64;
constexpr int M_   = B_ * T_;   // 8192

// ---------------------------------------------------------------------------
// Scratch
// ---------------------------------------------------------------------------
__device__ __half g_q[(size_t)M_ * KSZ];
__device__ __half g_k[(size_t)M_ * KSZ];
__device__ __half g_v[(size_t)M_ * KSZ];
__device__ float  g_attn[(size_t)M_ * KSZ];

// ---------------------------------------------------------------------------
// Helpers (base-PTX only: sm_103 target has no tcgen05)
// ---------------------------------------------------------------------------
__device__ __forceinline__ uint32_t smem_u32(const void* p) {
    uint32_t a;
    asm("{ .reg .u64 t; cvta.to.shared.u64 t, %1; cvt.u32.u64 %0, t; }" : "=r"(a) : "l"(p));
    return a;
}
__device__ __forceinline__ uint32_t tf32r(float x) {
    uint32_t u;
    asm("cvt.rna.tf32.f32 %0, %1;" : "=r"(u) : "f"(x));
    return u;
}
__device__ __forceinline__ void cp_async16(uint32_t dst, const void* src) {
    asm volatile("cp.async.cg.shared.global [%0], [%1], 16;" :: "r"(dst), "l"(src) : "memory");
}
#define CP_COMMIT()  asm volatile("cp.async.commit_group;" ::: "memory")
#define CP_WAIT_1()  asm volatile("cp.async.wait_group 1;" ::: "memory")

__device__ __forceinline__ void mma_tf32(float* d, const uint32_t* a, const uint32_t* b) {
    asm volatile(
        "mma.sync.aligned.m16n8k8.row.col.f32.tf32.tf32.f32 "
        "{%0,%1,%2,%3}, {%4,%5,%6,%7}, {%8,%9}, {%0,%1,%2,%3};"
        : "+f"(d[0]), "+f"(d[1]), "+f"(d[2]), "+f"(d[3])
        : "r"(a[0]), "r"(a[1]), "r"(a[2]), "r"(a[3]), "r"(b[0]), "r"(b[1]));
}
__device__ __forceinline__ void mma_f16(float* d, const uint32_t* a, const uint32_t* b) {
    asm volatile(
        "mma.sync.aligned.m16n8k16.row.col.f32.f16.f16.f32 "
        "{%0,%1,%2,%3}, {%4,%5,%6,%7}, {%8,%9}, {%0,%1,%2,%3};"
        : "+f"(d[0]), "+f"(d[1]), "+f"(d[2]), "+f"(d[3])
        : "r"(a[0]), "r"(a[1]), "r"(a[2]), "r"(a[3]), "r"(b[0]), "r"(b[1]));
}
__device__ __forceinline__ void ldsm_x4(uint32_t* d, uint32_t addr) {
    asm volatile("ldmatrix.sync.aligned.m8n8.x4.shared.b16 {%0,%1,%2,%3}, [%4];"
                 : "=r"(d[0]), "=r"(d[1]), "=r"(d[2]), "=r"(d[3]) : "r"(addr));
}
__device__ __forceinline__ void ldsm_x4_t(uint32_t* d, uint32_t addr) {
    asm volatile("ldmatrix.sync.aligned.m8n8.x4.trans.shared.b16 {%0,%1,%2,%3}, [%4];"
                 : "=r"(d[0]), "=r"(d[1]), "=r"(d[2]), "=r"(d[3]) : "r"(addr));
}

// ---------------------------------------------------------------------------
// tf32 mma.sync GEMM core (macro-free duplication via template on epilogue)
// M=8192, N=1024, K=1024. Block 128x128, BK=32, 3-stage cp.async pipeline.
// ---------------------------------------------------------------------------
constexpr int BM = 128, BN = 128, BK = 32, STAGES = 3;
constexpr int STAGE_FLOATS = (BM + BN) * BK;
constexpr int SM_GEMM_BYTES = STAGES * STAGE_FLOATS * 4;

template <typename OutT>
__global__ __launch_bounds__(256, 1)
void gemm_tf32_mma(const float* __restrict__ A, const float* __restrict__ W,
                   OutT* __restrict__ C) {
    extern __shared__ float smf[];
    const uint32_t sbase = smem_u32(smf);

    const int tid = threadIdx.x;
    const int wid = tid >> 5;
    const int lane = tid & 31;
    const int r = lane >> 2;
    const int c = lane & 3;
    const int wm = wid >> 2;
    const int wn = wid & 3;

    const int m0 = blockIdx.y * BM;
    const int n0 = blockIdx.x * BN;
    const int NIT = KSZ / BK;

    auto fetch_stage = [&](int kc, int s) {
        const uint32_t abase = sbase + (uint32_t)(s * STAGE_FLOATS) * 4u;
        const uint32_t bbase = abase + (uint32_t)(BM * BK) * 4u;
#pragma unroll
        for (int t = 0; t < 4; t++) {
            int idx = tid + t * 256;
            int row = idx >> 3;
            int c16 = idx & 7;
            uint32_t doff = (uint32_t)(row * 128 + ((c16 ^ (row & 7)) << 4));
            cp_async16(abase + doff, &A[(size_t)(m0 + row) * KSZ + kc * BK + c16 * 4]);
        }
#pragma unroll
        for (int t = 0; t < 4; t++) {
            int idx = tid + t * 256;
            int row = idx >> 3;
            int c16 = idx & 7;
            uint32_t doff = (uint32_t)(row * 128 + ((c16 ^ (row & 7)) << 4));
            cp_async16(bbase + doff, &W[(size_t)(n0 + row) * KSZ + kc * BK + c16 * 4]);
        }
    };

    float acc[4][4][4];
#pragma unroll
    for (int i = 0; i < 4; i++)
#pragma unroll
        for (int j = 0; j < 4; j++)
#pragma unroll
            for (int t = 0; t < 4; t++) acc[i][j][t] = 0.f;

    fetch_stage(0, 0); CP_COMMIT();
    fetch_stage(1, 1); CP_COMMIT();

    for (int kt = 0; kt < NIT; kt++) {
        CP_WAIT_1();
        __syncthreads();

        if (kt + 2 < NIT) fetch_stage(kt + 2, (kt + 2) % STAGES);
        CP_COMMIT();

        const int s = kt % STAGES;
        const float* As = smf + s * STAGE_FLOATS;
        const float* Bs = As + BM * BK;

#pragma unroll
        for (int ks = 0; ks < 4; ks++) {
            const int kx0 = c | ((((2 * ks) ^ r) & 7) << 2);
            const int kx1 = c | ((((2 * ks + 1) ^ r) & 7) << 2);

            uint32_t afr[4][4];
            uint32_t bfr[4][2];
#pragma unroll
            for (int i = 0; i < 4; i++) {
                const int m = wm * 64 + i * 16 + r;
                afr[i][0] = tf32r(As[m * 32 + kx0]);
                afr[i][1] = tf32r(As[(m + 8) * 32 + kx0]);
                afr[i][2] = tf32r(As[m * 32 + kx1]);
                afr[i][3] = tf32r(As[(m + 8) * 32 + kx1]);
            }
#pragma unroll
            for (int j = 0; j < 4; j++) {
                const int n = wn * 32 + j * 8 + r;
                bfr[j][0] = tf32r(Bs[n * 32 + kx0]);
                bfr[j][1] = tf32r(Bs[n * 32 + kx1]);
            }
#pragma unroll
            for (int i = 0; i < 4; i++)
#pragma unroll
                for (int j = 0; j < 4; j++)
                    mma_tf32(acc[i][j], afr[i], bfr[j]);
        }
        __syncthreads();
    }

#pragma unroll
    for (int i = 0; i < 4; i++) {
        const int row = m0 + wm * 64 + i * 16 + r;
#pragma unroll
        for (int j = 0; j < 4; j++) {
            const int col = n0 + wn * 32 + j * 8 + c * 2;
            if constexpr (sizeof(OutT) == 4) {
                float* p0 = (float*)C + (size_t)row * KSZ + col;
                float* p1 = (float*)C + (size_t)(row + 8) * KSZ + col;
                asm volatile("st.global.v2.f32 [%0], {%1,%2};" :: "l"(p0),
                             "f"(acc[i][j][0]), "f"(acc[i][j][1]) : "memory");
                asm volatile("st.global.v2.f32 [%0], {%1,%2};" :: "l"(p1),
                             "f"(acc[i][j][2]), "f"(acc[i][j][3]) : "memory");
            } else {
                __half2 h01 = __floats2half2_rn(acc[i][j][0], acc[i][j][1]);
                __half2 h23 = __floats2half2_rn(acc[i][j][2], acc[i][j][3]);
                *reinterpret_cast<__half2*>((__half*)C + (size_t)row * KSZ + col) = h01;
                *reinterpret_cast<__half2*>((__half*)C + (size_t)(row + 8) * KSZ + col) = h23;
            }
        }
    }
}

// ---------------------------------------------------------------------------
// fp16 flash attention, register-resident P, ldmatrix K/V fragments.
// CTA: one (b,h) x 128 query rows, 8 warps x 16 rows. 64-key chunks,
// 2-stage cp.async double buffer. smem = K + V only (2 x 9216 B each).
// K/V rows padded to 72 halves (144 B) -> ldsm rows land on distinct banks.
// ---------------------------------------------------------------------------
constexpr int KV_PITCH_H = 72;                         // halves per row
constexpr int KV_ROW_B   = KV_PITCH_H * 2;             // 144 bytes
constexpr int KV_STAGE_B = 64 * KV_ROW_B;              // 9216
constexpr int AOFF_K = 0;
constexpr int AOFF_V = 2 * KV_STAGE_B;                 // 18432
constexpr int ATTN_SMEM_B = 4 * KV_STAGE_B;            // 36864

__global__ __launch_bounds__(256, 2)
void attn_f16_kernel(const __half* __restrict__ q, const __half* __restrict__ k,
                     const __half* __restrict__ v, float* __restrict__ o) {
    extern __shared__ char smc[];
    const uint32_t sbase = smem_u32(smc);

    const int tid = threadIdx.x;
    const int wid = tid >> 5;
    const int lane = tid & 31;
    const int r = lane >> 2;      // 0..7
    const int c = lane & 3;       // 0..3
    const int i2 = lane & 7;      // ldsm row-within-8
    const int sel = lane >> 3;    // ldsm matrix selector 0..3
    const int wrow = wid * 16;

    const int bh = blockIdx.y;
    const int b  = bh >> 4;
    const int h  = bh & 15;
    const int m0 = blockIdx.x * 128;

    const __half* qg = q + ((size_t)(b * T_) + m0) * KSZ + h * DK_;
    const __half* kg0 = k + ((size_t)(b * C_)) * KSZ + h * DK_;
    const __half* vg0 = v + ((size_t)(b * C_)) * KSZ + h * DK_;

    auto fetchKV = [&](int ch, int s) {
        const __half* kg = kg0 + (size_t)(ch * 64) * KSZ;
        const __half* vg = vg0 + (size_t)(ch * 64) * KSZ;
        const uint32_t kb = sbase + AOFF_K + (uint32_t)s * KV_STAGE_B;
        const uint32_t vb = sbase + AOFF_V + (uint32_t)s * KV_STAGE_B;
#pragma unroll
        for (int t = 0; t < 2; t++) {
            int idx = tid + t * 256;          // 0..511
            int row = idx >> 3;               // 0..63
            int c8  = idx & 7;                // 16B chunk (8 halves)
            cp_async16(kb + (uint32_t)(row * KV_ROW_B + c8 * 16),
                       kg + (size_t)row * KSZ + c8 * 8);
            cp_async16(vb + (uint32_t)(row * KV_ROW_B + c8 * 16),
                       vg + (size_t)row * KSZ + c8 * 8);
        }
    };

    // Q fragments straight from global (one-time; chunk-invariant)
    uint32_t qfr[4][4];
#pragma unroll
    for (int ks = 0; ks < 4; ks++) {
        qfr[ks][0] = *reinterpret_cast<const uint32_t*>(&qg[(size_t)(wrow + r) * KSZ + ks * 16 + 2 * c]);
        qfr[ks][1] = *reinterpret_cast<const uint32_t*>(&qg[(size_t)(wrow + r + 8) * KSZ + ks * 16 + 2 * c]);
        qfr[ks][2] = *reinterpret_cast<const uint32_t*>(&qg[(size_t)(wrow + r) * KSZ + ks * 16 + 2 * c + 8]);
        qfr[ks][3] = *reinterpret_cast<const uint32_t*>(&qg[(size_t)(wrow + r + 8) * KSZ + ks * 16 + 2 * c + 8]);
    }

    fetchKV(0, 0);
    CP_COMMIT();

    float oacc[8][4];
    float mi0 = -1e30f, mi1 = -1e30f, li0 = 0.f, li1 = 0.f;
#pragma unroll
    for (int j = 0; j < 8; j++)
#pragma unroll
        for (int t = 0; t < 4; t++) oacc[j][t] = 0.f;

    // ldsm per-thread address components
    const uint32_t k_row = (uint32_t)(i2 + ((sel >> 1) << 3));   // + jp*8
    const uint32_t k_col = (uint32_t)((sel & 1) << 3);           // + ks*16
    const uint32_t v_row = (uint32_t)(i2 + ((sel & 1) << 3));    // + kx*16
    const uint32_t v_col = (uint32_t)((sel >> 1) << 3);          // + jp*8

    const int NC = C_ / 64;   // 32
    for (int ch = 0; ch < NC; ch++) {
        if (ch + 1 < NC) fetchKV(ch + 1, (ch + 1) & 1);
        CP_COMMIT();
        CP_WAIT_1();
        __syncthreads();

        const uint32_t Kc = sbase + AOFF_K + (uint32_t)(ch & 1) * KV_STAGE_B;
        const uint32_t Vc = sbase + AOFF_V + (uint32_t)(ch & 1) * KV_STAGE_B;

        // ---- S = Q K^T  (fp16 MMA, fp32 accum) ----
        float sacc[8][4];
#pragma unroll
        for (int j = 0; j < 8; j++)
#pragma unroll
            for (int t = 0; t < 4; t++) sacc[j][t] = 0.f;

#pragma unroll
        for (int ks = 0; ks < 4; ks++) {
#pragma unroll
            for (int jp = 0; jp < 8; jp += 2) {
                uint32_t kf[4];
                uint32_t addr = Kc + (jp * 8 + k_row) * KV_ROW_B + (ks * 16 + k_col) * 2;
                ldsm_x4(kf, addr);
                mma_f16(sacc[jp],     qfr[ks], kf + 0);
                mma_f16(sacc[jp + 1], qfr[ks], kf + 2);
            }
        }

        // ---- online softmax (rows wrow+r, wrow+r+8) ----
        float mx0 = -1e30f, mx1 = -1e30f;
#pragma unroll
        for (int j = 0; j < 8; j++) {
            sacc[j][0] *= 0.125f; sacc[j][1] *= 0.125f;
            sacc[j][2] *= 0.125f; sacc[j][3] *= 0.125f;
            mx0 = fmaxf(mx0, fmaxf(sacc[j][0], sacc[j][1]));
            mx1 = fmaxf(mx1, fmaxf(sacc[j][2], sacc[j][3]));
        }
        mx0 = fmaxf(mx0, __shfl_xor_sync(0xffffffffu, mx0, 1));
        mx0 = fmaxf(mx0, __shfl_xor_sync(0xffffffffu, mx0, 2));
        mx1 = fmaxf(mx1, __shfl_xor_sync(0xffffffffu, mx1, 1));
        mx1 = fmaxf(mx1, __shfl_xor_sync(0xffffffffu, mx1, 2));

        const float nm0 = fmaxf(mi0, mx0);
        const float nm1 = fmaxf(mi1, mx1);
        const float corr0 = __expf(mi0 - nm0);
        const float corr1 = __expf(mi1 - nm1);
        mi0 = nm0; mi1 = nm1;

        float ls0 = 0.f, ls1 = 0.f;
#pragma unroll
        for (int j = 0; j < 8; j++) {
            sacc[j][0] = __expf(sacc[j][0] - nm0);
            sacc[j][1] = __expf(sacc[j][1] - nm0);
            sacc[j][2] = __expf(sacc[j][2] - nm1);
            sacc[j][3] = __expf(sacc[j][3] - nm1);
            ls0 += sacc[j][0] + sacc[j][1];
            ls1 += sacc[j][2] + sacc[j][3];
        }
        ls0 += __shfl_xor_sync(0xffffffffu, ls0, 1);
        ls0 += __shfl_xor_sync(0xffffffffu, ls0, 2);
        ls1 += __shfl_xor_sync(0xffffffffu, ls1, 1);
        ls1 += __shfl_xor_sync(0xffffffffu, ls1, 2);
        li0 = li0 * corr0 + ls0;
        li1 = li1 * corr1 + ls1;

#pragma unroll
        for (int j = 0; j < 8; j++) {
            oacc[j][0] *= corr0; oacc[j][1] *= corr0;
            oacc[j][2] *= corr1; oacc[j][3] *= corr1;
        }

        // ---- P: pack to fp16 in registers (no smem!) ----
        uint32_t pfr[4][4];
#pragma unroll
        for (int kx = 0; kx < 4; kx++) {
            __half2 h;
            h = __floats2half2_rn(sacc[2 * kx][0], sacc[2 * kx][1]);
            pfr[kx][0] = *reinterpret_cast<uint32_t*>(&h);
            h = __floats2half2_rn(sacc[2 * kx][2], sacc[2 * kx][3]);
            pfr[kx][1] = *reinterpret_cast<uint32_t*>(&h);
            h = __floats2half2_rn(sacc[2 * kx + 1][0], sacc[2 * kx + 1][1]);
            pfr[kx][2] = *reinterpret_cast<uint32_t*>(&h);
            h = __floats2half2_rn(sacc[2 * kx + 1][2], sacc[2 * kx + 1][3]);
            pfr[kx][3] = *reinterpret_cast<uint32_t*>(&h);
        }

        // ---- O += P V  (V fragments via ldmatrix.trans) ----
#pragma unroll
        for (int kx = 0; kx < 4; kx++) {
#pragma unroll
            for (int jp = 0; jp < 8; jp += 2) {
                uint32_t vf[4];
                uint32_t addr = Vc + (kx * 16 + v_row) * KV_ROW_B + (jp * 8 + v_col) * 2;
                ldsm_x4_t(vf, addr);
                mma_f16(oacc[jp],     pfr[kx], vf + 0);
                mma_f16(oacc[jp + 1], pfr[kx], vf + 2);
            }
        }

        __syncthreads();   // all warps done with this K/V buffer before refill
    }

    // ---- epilogue ----
    const float inv0 = 1.f / li0;
    const float inv1 = 1.f / li1;
    float* og = o + ((size_t)(b * T_) + m0) * KSZ + h * DK_;
#pragma unroll
    for (int j = 0; j < 8; j++) {
        float* p0 = og + (size_t)(wrow + r) * KSZ + j * 8 + 2 * c;
        float* p1 = og + (size_t)(wrow + r + 8) * KSZ + j * 8 + 2 * c;
        asm volatile("st.global.v2.f32 [%0], {%1,%2};" :: "l"(p0),
                     "f"(oacc[j][0] * inv0), "f"(oacc[j][1] * inv0) : "memory");
        asm volatile("st.global.v2.f32 [%0], {%1,%2};" :: "l"(p1),
                     "f"(oacc[j][2] * inv1), "f"(oacc[j][3] * inv1) : "memory");
    }
}

// ---------------------------------------------------------------------------
// Launch
// ---------------------------------------------------------------------------
extern "C" void kernel_launch(void* const* d_in, const int* /*in_sizes*/, int /*n_in*/,
                              void* d_out, int /*out_size*/) {
    const float* queries = (const float*)d_in[0];
    const float* keys    = (const float*)d_in[1];
    const float* values  = (const float*)d_in[2];
    const float* Wq      = (const float*)d_in[3];
    const float* Wk      = (const float*)d_in[4];
    const float* Wv      = (const float*)d_in[5];
    const float* Wo      = (const float*)d_in[6];
    float* out = (float*)d_out;

    __half *qb, *kb, *vb;
    float *ab;
    cudaGetSymbolAddress((void**)&qb, g_q);
    cudaGetSymbolAddress((void**)&kb, g_k);
    cudaGetSymbolAddress((void**)&vb, g_v);
    cudaGetSymbolAddress((void**)&ab, g_attn);

    cudaFuncSetAttribute(gemm_tf32_mma<__half>, cudaFuncAttributeMaxDynamicSharedMemorySize,
                         SM_GEMM_BYTES);
    cudaFuncSetAttribute(gemm_tf32_mma<float>, cudaFuncAttributeMaxDynamicSharedMemorySize,
                         SM_GEMM_BYTES);
    cudaFuncSetAttribute(attn_f16_kernel, cudaFuncAttributeMaxDynamicSharedMemorySize,
                         ATTN_SMEM_B);

    dim3 gg(KSZ / BN, M_ / BM);   // (8, 64)

    gemm_tf32_mma<__half><<<gg, 256, SM_GEMM_BYTES>>>(queries, Wq, qb);
    gemm_tf32_mma<__half><<<gg, 256, SM_GEMM_BYTES>>>(keys,    Wk, kb);
    gemm_tf32_mma<__half><<<gg, 256, SM_GEMM_BYTES>>>(values,  Wv, vb);

    attn_f16_kernel<<<dim3(T_ / 128, B_ * H_), 256, ATTN_SMEM_B>>>(qb, kb, vb, ab);

    gemm_tf32_mma<float><<<gg, 256, SM_GEMM_BYTES>>>(ab, Wo, out);
}

// round 9
// speedup vs baseline: 7.8411x; 1.5101x over previous
#include <cuda_runtime.h>
#include <cuda_fp16.h>
#include <cstdint>
#include <cstddef>

// Problem constants
constexpr int B_   = 4;
constexpr int T_   = 2048;
constexpr int C_   = 2048;
constexpr int KSZ  = 1024;
constexpr int H_   = 16;
constexpr int DK_  = 64;
constexpr int M_   = B_ * T_;   // 8192

// ---------------------------------------------------------------------------
// Scratch (all fp16)
// ---------------------------------------------------------------------------
__device__ __half g_qin[(size_t)M_ * KSZ];
__device__ __half g_kin[(size_t)M_ * KSZ];
__device__ __half g_vin[(size_t)M_ * KSZ];
__device__ __half g_wq[(size_t)KSZ * KSZ];
__device__ __half g_wk[(size_t)KSZ * KSZ];
__device__ __half g_wv[(size_t)KSZ * KSZ];
__device__ __half g_wo[(size_t)KSZ * KSZ];
__device__ __half g_q[(size_t)M_ * KSZ];
__device__ __half g_k[(size_t)M_ * KSZ];
__device__ __half g_v[(size_t)M_ * KSZ];
__device__ __half g_attnh[(size_t)M_ * KSZ];

// ---------------------------------------------------------------------------
// Helpers
// ---------------------------------------------------------------------------
__device__ __forceinline__ uint32_t smem_u32(const void* p) {
    uint32_t a;
    asm("{ .reg .u64 t; cvta.to.shared.u64 t, %1; cvt.u32.u64 %0, t; }" : "=r"(a) : "l"(p));
    return a;
}
__device__ __forceinline__ void cp_async16(uint32_t dst, const void* src) {
    asm volatile("cp.async.cg.shared.global [%0], [%1], 16;" :: "r"(dst), "l"(src) : "memory");
}
#define CP_COMMIT()  asm volatile("cp.async.commit_group;" ::: "memory")
#define CP_WAIT_1()  asm volatile("cp.async.wait_group 1;" ::: "memory")

__device__ __forceinline__ void mma_f16(float* d, const uint32_t* a, const uint32_t* b) {
    asm volatile(
        "mma.sync.aligned.m16n8k16.row.col.f32.f16.f16.f32 "
        "{%0,%1,%2,%3}, {%4,%5,%6,%7}, {%8,%9}, {%0,%1,%2,%3};"
        : "+f"(d[0]), "+f"(d[1]), "+f"(d[2]), "+f"(d[3])
        : "r"(a[0]), "r"(a[1]), "r"(a[2]), "r"(a[3]), "r"(b[0]), "r"(b[1]));
}
__device__ __forceinline__ void ldsm_x4(uint32_t* d, uint32_t addr) {
    asm volatile("ldmatrix.sync.aligned.m8n8.x4.shared.b16 {%0,%1,%2,%3}, [%4];"
                 : "=r"(d[0]), "=r"(d[1]), "=r"(d[2]), "=r"(d[3]) : "r"(addr));
}
__device__ __forceinline__ void ldsm_x4_t(uint32_t* d, uint32_t addr) {
    asm volatile("ldmatrix.sync.aligned.m8n8.x4.trans.shared.b16 {%0,%1,%2,%3}, [%4];"
                 : "=r"(d[0]), "=r"(d[1]), "=r"(d[2]), "=r"(d[3]) : "r"(addr));
}

// ---------------------------------------------------------------------------
// fp32 -> fp16 elementwise convert (8 elems / thread)
// ---------------------------------------------------------------------------
__global__ __launch_bounds__(256)
void f2h_kernel(const float* __restrict__ src, __half* __restrict__ dst, int n8) {
    int i = blockIdx.x * blockDim.x + threadIdx.x;
    if (i < n8) {
        float4 v0 = reinterpret_cast<const float4*>(src)[2 * i];
        float4 v1 = reinterpret_cast<const float4*>(src)[2 * i + 1];
        __half2 h0 = __floats2half2_rn(v0.x, v0.y);
        __half2 h1 = __floats2half2_rn(v0.z, v0.w);
        __half2 h2 = __floats2half2_rn(v1.x, v1.y);
        __half2 h3 = __floats2half2_rn(v1.z, v1.w);
        uint4 o;
        o.x = *reinterpret_cast<uint32_t*>(&h0);
        o.y = *reinterpret_cast<uint32_t*>(&h1);
        o.z = *reinterpret_cast<uint32_t*>(&h2);
        o.w = *reinterpret_cast<uint32_t*>(&h3);
        reinterpret_cast<uint4*>(dst)[i] = o;
    }
}

// ---------------------------------------------------------------------------
// fp16 mma.sync GEMM:  C[m][n] = sum_k A[m][k] * W[n][k]   (NT)
// M=8192, N=1024, K=1024. Block 128x128, BK=64, 3-stage cp.async.
// 8 warps 2(m) x 4(n); warp tile 64x32. Fragments via ldmatrix.x4.
// Smem rows padded to 72 halves (144 B) -> conflict-free ldsm.
// ---------------------------------------------------------------------------
constexpr int GBM = 128, GBN = 128, GBK = 64;
constexpr int GROW_B   = 144;                    // bytes per padded row
constexpr int GSTAGE_B = (GBM + GBN) * GROW_B;   // 36864
constexpr int GSMEM_B  = 3 * GSTAGE_B;           // 110592

template <typename OutT>
__global__ __launch_bounds__(256, 2)
void gemm_f16(const __half* __restrict__ A, const __half* __restrict__ W,
              OutT* __restrict__ C) {
    extern __shared__ char smc[];
    const uint32_t sbase = smem_u32(smc);

    const int tid = threadIdx.x;
    const int wid = tid >> 5;
    const int lane = tid & 31;
    const int r = lane >> 2;
    const int c = lane & 3;
    const int i2 = lane & 7;
    const int sel = lane >> 3;
    const int wm = wid >> 2;      // 0..1
    const int wn = wid & 3;       // 0..3

    const int m0 = blockIdx.y * GBM;
    const int n0 = blockIdx.x * GBN;
    const int NIT = KSZ / GBK;    // 16

    auto fetch_stage = [&](int kc, int s) {
        const uint32_t abase = sbase + (uint32_t)s * GSTAGE_B;
        const uint32_t bbase = abase + GBM * GROW_B;
#pragma unroll
        for (int t = 0; t < 4; t++) {
            int idx = tid + t * 256;
            int row = idx >> 3;             // 0..127
            int c8  = idx & 7;              // 16B chunk (8 halves)
            cp_async16(abase + (uint32_t)(row * GROW_B + c8 * 16),
                       A + (size_t)(m0 + row) * KSZ + kc * GBK + c8 * 8);
        }
#pragma unroll
        for (int t = 0; t < 4; t++) {
            int idx = tid + t * 256;
            int row = idx >> 3;
            int c8  = idx & 7;
            cp_async16(bbase + (uint32_t)(row * GROW_B + c8 * 16),
                       W + (size_t)(n0 + row) * KSZ + kc * GBK + c8 * 8);
        }
    };

    // ldsm lane address components
    const uint32_t a_off = (uint32_t)((i2 + ((sel & 1) << 3)) * GROW_B + (((sel >> 1) << 3) << 1));
    const uint32_t b_off = (uint32_t)((i2 + ((sel >> 1) << 3)) * GROW_B + (((sel & 1) << 3) << 1));

    float acc[4][4][4];
#pragma unroll
    for (int i = 0; i < 4; i++)
#pragma unroll
        for (int j = 0; j < 4; j++)
#pragma unroll
            for (int t = 0; t < 4; t++) acc[i][j][t] = 0.f;

    fetch_stage(0, 0); CP_COMMIT();
    fetch_stage(1, 1); CP_COMMIT();

    for (int kt = 0; kt < NIT; kt++) {
        CP_WAIT_1();
        __syncthreads();

        if (kt + 2 < NIT) fetch_stage(kt + 2, (kt + 2) % 3);
        CP_COMMIT();

        const int s = kt % 3;
        const uint32_t As = sbase + (uint32_t)s * GSTAGE_B;
        const uint32_t Bs = As + GBM * GROW_B;
        const uint32_t Aw = As + (uint32_t)(wm * 64) * GROW_B + a_off;
        const uint32_t Bw = Bs + (uint32_t)(wn * 32) * GROW_B + b_off;

#pragma unroll
        for (int ks = 0; ks < 4; ks++) {
            uint32_t afr[4][4];
#pragma unroll
            for (int i = 0; i < 4; i++)
                ldsm_x4(afr[i], Aw + (uint32_t)(i * 16) * GROW_B + ks * 32);
            uint32_t bfr[8];
            ldsm_x4(bfr,     Bw + ks * 32);
            ldsm_x4(bfr + 4, Bw + (uint32_t)(16 * GROW_B) + ks * 32);
#pragma unroll
            for (int i = 0; i < 4; i++)
#pragma unroll
                for (int j = 0; j < 4; j++)
                    mma_f16(acc[i][j], afr[i], bfr + j * 2);
        }
        __syncthreads();
    }

#pragma unroll
    for (int i = 0; i < 4; i++) {
        const int row = m0 + wm * 64 + i * 16 + r;
#pragma unroll
        for (int j = 0; j < 4; j++) {
            const int col = n0 + wn * 32 + j * 8 + c * 2;
            if constexpr (sizeof(OutT) == 4) {
                float* p0 = (float*)C + (size_t)row * KSZ + col;
                float* p1 = (float*)C + (size_t)(row + 8) * KSZ + col;
                asm volatile("st.global.v2.f32 [%0], {%1,%2};" :: "l"(p0),
                             "f"(acc[i][j][0]), "f"(acc[i][j][1]) : "memory");
                asm volatile("st.global.v2.f32 [%0], {%1,%2};" :: "l"(p1),
                             "f"(acc[i][j][2]), "f"(acc[i][j][3]) : "memory");
            } else {
                __half2 h01 = __floats2half2_rn(acc[i][j][0], acc[i][j][1]);
                __half2 h23 = __floats2half2_rn(acc[i][j][2], acc[i][j][3]);
                *reinterpret_cast<__half2*>((__half*)C + (size_t)row * KSZ + col) = h01;
                *reinterpret_cast<__half2*>((__half*)C + (size_t)(row + 8) * KSZ + col) = h23;
            }
        }
    }
}

// ---------------------------------------------------------------------------
// fp16 flash attention (round-6 kernel; epilogue now writes fp16)
// ---------------------------------------------------------------------------
constexpr int KV_PITCH_H = 72;
constexpr int KV_ROW_B   = KV_PITCH_H * 2;
constexpr int KV_STAGE_B = 64 * KV_ROW_B;
constexpr int AOFF_K = 0;
constexpr int AOFF_V = 2 * KV_STAGE_B;
constexpr int ATTN_SMEM_B = 4 * KV_STAGE_B;

__global__ __launch_bounds__(256, 2)
void attn_f16_kernel(const __half* __restrict__ q, const __half* __restrict__ k,
                     const __half* __restrict__ v, __half* __restrict__ o) {
    extern __shared__ char smc[];
    const uint32_t sbase = smem_u32(smc);

    const int tid = threadIdx.x;
    const int wid = tid >> 5;
    const int lane = tid & 31;
    const int r = lane >> 2;
    const int c = lane & 3;
    const int i2 = lane & 7;
    const int sel = lane >> 3;
    const int wrow = wid * 16;

    const int bh = blockIdx.y;
    const int b  = bh >> 4;
    const int h  = bh & 15;
    const int m0 = blockIdx.x * 128;

    const __half* qg = q + ((size_t)(b * T_) + m0) * KSZ + h * DK_;
    const __half* kg0 = k + ((size_t)(b * C_)) * KSZ + h * DK_;
    const __half* vg0 = v + ((size_t)(b * C_)) * KSZ + h * DK_;

    auto fetchKV = [&](int ch, int s) {
        const __half* kg = kg0 + (size_t)(ch * 64) * KSZ;
        const __half* vg = vg0 + (size_t)(ch * 64) * KSZ;
        const uint32_t kb = sbase + AOFF_K + (uint32_t)s * KV_STAGE_B;
        const uint32_t vb = sbase + AOFF_V + (uint32_t)s * KV_STAGE_B;
#pragma unroll
        for (int t = 0; t < 2; t++) {
            int idx = tid + t * 256;
            int row = idx >> 3;
            int c8  = idx & 7;
            cp_async16(kb + (uint32_t)(row * KV_ROW_B + c8 * 16),
                       kg + (size_t)row * KSZ + c8 * 8);
            cp_async16(vb + (uint32_t)(row * KV_ROW_B + c8 * 16),
                       vg + (size_t)row * KSZ + c8 * 8);
        }
    };

    uint32_t qfr[4][4];
#pragma unroll
    for (int ks = 0; ks < 4; ks++) {
        qfr[ks][0] = *reinterpret_cast<const uint32_t*>(&qg[(size_t)(wrow + r) * KSZ + ks * 16 + 2 * c]);
        qfr[ks][1] = *reinterpret_cast<const uint32_t*>(&qg[(size_t)(wrow + r + 8) * KSZ + ks * 16 + 2 * c]);
        qfr[ks][2] = *reinterpret_cast<const uint32_t*>(&qg[(size_t)(wrow + r) * KSZ + ks * 16 + 2 * c + 8]);
        qfr[ks][3] = *reinterpret_cast<const uint32_t*>(&qg[(size_t)(wrow + r + 8) * KSZ + ks * 16 + 2 * c + 8]);
    }

    fetchKV(0, 0);
    CP_COMMIT();

    float oacc[8][4];
    float mi0 = -1e30f, mi1 = -1e30f, li0 = 0.f, li1 = 0.f;
#pragma unroll
    for (int j = 0; j < 8; j++)
#pragma unroll
        for (int t = 0; t < 4; t++) oacc[j][t] = 0.f;

    const uint32_t k_row = (uint32_t)(i2 + ((sel >> 1) << 3));
    const uint32_t k_col = (uint32_t)((sel & 1) << 3);
    const uint32_t v_row = (uint32_t)(i2 + ((sel & 1) << 3));
    const uint32_t v_col = (uint32_t)((sel >> 1) << 3);

    const int NC = C_ / 64;
    for (int ch = 0; ch < NC; ch++) {
        if (ch + 1 < NC) fetchKV(ch + 1, (ch + 1) & 1);
        CP_COMMIT();
        CP_WAIT_1();
        __syncthreads();

        const uint32_t Kc = sbase + AOFF_K + (uint32_t)(ch & 1) * KV_STAGE_B;
        const uint32_t Vc = sbase + AOFF_V + (uint32_t)(ch & 1) * KV_STAGE_B;

        float sacc[8][4];
#pragma unroll
        for (int j = 0; j < 8; j++)
#pragma unroll
            for (int t = 0; t < 4; t++) sacc[j][t] = 0.f;

#pragma unroll
        for (int ks = 0; ks < 4; ks++) {
#pragma unroll
            for (int jp = 0; jp < 8; jp += 2) {
                uint32_t kf[4];
                uint32_t addr = Kc + (jp * 8 + k_row) * KV_ROW_B + (ks * 16 + k_col) * 2;
                ldsm_x4(kf, addr);
                mma_f16(sacc[jp],     qfr[ks], kf + 0);
                mma_f16(sacc[jp + 1], qfr[ks], kf + 2);
            }
        }

        float mx0 = -1e30f, mx1 = -1e30f;
#pragma unroll
        for (int j = 0; j < 8; j++) {
            sacc[j][0] *= 0.125f; sacc[j][1] *= 0.125f;
            sacc[j][2] *= 0.125f; sacc[j][3] *= 0.125f;
            mx0 = fmaxf(mx0, fmaxf(sacc[j][0], sacc[j][1]));
            mx1 = fmaxf(mx1, fmaxf(sacc[j][2], sacc[j][3]));
        }
        mx0 = fmaxf(mx0, __shfl_xor_sync(0xffffffffu, mx0, 1));
        mx0 = fmaxf(mx0, __shfl_xor_sync(0xffffffffu, mx0, 2));
        mx1 = fmaxf(mx1, __shfl_xor_sync(0xffffffffu, mx1, 1));
        mx1 = fmaxf(mx1, __shfl_xor_sync(0xffffffffu, mx1, 2));

        const float nm0 = fmaxf(mi0, mx0);
        const float nm1 = fmaxf(mi1, mx1);
        const float corr0 = __expf(mi0 - nm0);
        const float corr1 = __expf(mi1 - nm1);
        mi0 = nm0; mi1 = nm1;

        float ls0 = 0.f, ls1 = 0.f;
#pragma unroll
        for (int j = 0; j < 8; j++) {
            sacc[j][0] = __expf(sacc[j][0] - nm0);
            sacc[j][1] = __expf(sacc[j][1] - nm0);
            sacc[j][2] = __expf(sacc[j][2] - nm1);
            sacc[j][3] = __expf(sacc[j][3] - nm1);
            ls0 += sacc[j][0] + sacc[j][1];
            ls1 += sacc[j][2] + sacc[j][3];
        }
        ls0 += __shfl_xor_sync(0xffffffffu, ls0, 1);
        ls0 += __shfl_xor_sync(0xffffffffu, ls0, 2);
        ls1 += __shfl_xor_sync(0xffffffffu, ls1, 1);
        ls1 += __shfl_xor_sync(0xffffffffu, ls1, 2);
        li0 = li0 * corr0 + ls0;
        li1 = li1 * corr1 + ls1;

#pragma unroll
        for (int j = 0; j < 8; j++) {
            oacc[j][0] *= corr0; oacc[j][1] *= corr0;
            oacc[j][2] *= corr1; oacc[j][3] *= corr1;
        }

        uint32_t pfr[4][4];
#pragma unroll
        for (int kx = 0; kx < 4; kx++) {
            __half2 hh;
            hh = __floats2half2_rn(sacc[2 * kx][0], sacc[2 * kx][1]);
            pfr[kx][0] = *reinterpret_cast<uint32_t*>(&hh);
            hh = __floats2half2_rn(sacc[2 * kx][2], sacc[2 * kx][3]);
            pfr[kx][1] = *reinterpret_cast<uint32_t*>(&hh);
            hh = __floats2half2_rn(sacc[2 * kx + 1][0], sacc[2 * kx + 1][1]);
            pfr[kx][2] = *reinterpret_cast<uint32_t*>(&hh);
            hh = __floats2half2_rn(sacc[2 * kx + 1][2], sacc[2 * kx + 1][3]);
            pfr[kx][3] = *reinterpret_cast<uint32_t*>(&hh);
        }

#pragma unroll
        for (int kx = 0; kx < 4; kx++) {
#pragma unroll
            for (int jp = 0; jp < 8; jp += 2) {
                uint32_t vf[4];
                uint32_t addr = Vc + (kx * 16 + v_row) * KV_ROW_B + (jp * 8 + v_col) * 2;
                ldsm_x4_t(vf, addr);
                mma_f16(oacc[jp],     pfr[kx], vf + 0);
                mma_f16(oacc[jp + 1], pfr[kx], vf + 2);
            }
        }

        __syncthreads();
    }

    const float inv0 = 1.f / li0;
    const float inv1 = 1.f / li1;
    __half* og = o + ((size_t)(b * T_) + m0) * KSZ + h * DK_;
#pragma unroll
    for (int j = 0; j < 8; j++) {
        __half2 h0 = __floats2half2_rn(oacc[j][0] * inv0, oacc[j][1] * inv0);
        __half2 h1 = __floats2half2_rn(oacc[j][2] * inv1, oacc[j][3] * inv1);
        *reinterpret_cast<__half2*>(og + (size_t)(wrow + r) * KSZ + j * 8 + 2 * c) = h0;
        *reinterpret_cast<__half2*>(og + (size_t)(wrow + r + 8) * KSZ + j * 8 + 2 * c) = h1;
    }
}

// ---------------------------------------------------------------------------
// Launch
// ---------------------------------------------------------------------------
extern "C" void kernel_launch(void* const* d_in, const int* /*in_sizes*/, int /*n_in*/,
                              void* d_out, int /*out_size*/) {
    const float* queries = (const float*)d_in[0];
    const float* keys    = (const float*)d_in[1];
    const float* values  = (const float*)d_in[2];
    const float* Wq      = (const float*)d_in[3];
    const float* Wk      = (const float*)d_in[4];
    const float* Wv      = (const float*)d_in[5];
    const float* Wo      = (const float*)d_in[6];
    float* out = (float*)d_out;

    __half *qin, *kin, *vin, *wq, *wk, *wv, *wo, *qb, *kb, *vb, *ah;
    cudaGetSymbolAddress((void**)&qin, g_qin);
    cudaGetSymbolAddress((void**)&kin, g_kin);
    cudaGetSymbolAddress((void**)&vin, g_vin);
    cudaGetSymbolAddress((void**)&wq,  g_wq);
    cudaGetSymbolAddress((void**)&wk,  g_wk);
    cudaGetSymbolAddress((void**)&wv,  g_wv);
    cudaGetSymbolAddress((void**)&wo,  g_wo);
    cudaGetSymbolAddress((void**)&qb,  g_q);
    cudaGetSymbolAddress((void**)&kb,  g_k);
    cudaGetSymbolAddress((void**)&vb,  g_v);
    cudaGetSymbolAddress((void**)&ah,  g_attnh);

    cudaFuncSetAttribute(gemm_f16<__half>, cudaFuncAttributeMaxDynamicSharedMemorySize, GSMEM_B);
    cudaFuncSetAttribute(gemm_f16<float>,  cudaFuncAttributeMaxDynamicSharedMemorySize, GSMEM_B);
    cudaFuncSetAttribute(attn_f16_kernel,  cudaFuncAttributeMaxDynamicSharedMemorySize, ATTN_SMEM_B);

    const int nBig = M_ * KSZ / 8;      // 1M vec8 per activation tensor
    const int nW   = KSZ * KSZ / 8;     // 128K vec8 per weight
    f2h_kernel<<<(nBig + 255) / 256, 256>>>(queries, qin, nBig);
    f2h_kernel<<<(nBig + 255) / 256, 256>>>(keys,    kin, nBig);
    f2h_kernel<<<(nBig + 255) / 256, 256>>>(values,  vin, nBig);
    f2h_kernel<<<(nW + 255) / 256, 256>>>(Wq, wq, nW);
    f2h_kernel<<<(nW + 255) / 256, 256>>>(Wk, wk, nW);
    f2h_kernel<<<(nW + 255) / 256, 256>>>(Wv, wv, nW);
    f2h_kernel<<<(nW + 255) / 256, 256>>>(Wo, wo, nW);

    dim3 gg(KSZ / GBN, M_ / GBM);   // (8, 64)

    gemm_f16<__half><<<gg, 256, GSMEM_B>>>(qin, wq, qb);
    gemm_f16<__half><<<gg, 256, GSMEM_B>>>(kin, wk, kb);
    gemm_f16<__half><<<gg, 256, GSMEM_B>>>(vin, wv, vb);

    attn_f16_kernel<<<dim3(T_ / 128, B_ * H_), 256, ATTN_SMEM_B>>>(qb, kb, vb, ah);

    gemm_f16<float><<<gg, 256, GSMEM_B>>>(ah, wo, out);
}